// round 16
// baseline (speedup 1.0000x reference)
#include <cuda_runtime.h>
#include <cuda_fp16.h>
#include <mma.h>
#include <cstdint>

using namespace nvcuda;

// ---------------------------------------------------------------------------
// GraphSAGE 3-layer, aggregate-then-transform, fp16 activations.
// R16: each layer split into
//   yr-pass   : yr = H@Wrh + H@Wrl          (main stream, graph-independent)
//   gather    : G  = sum_neigh(H)           (aux stream, CONCURRENT with yr)
//   final-pass: h' = act(G/deg@Wlh + G/deg@Wll + yr + b)
// Layer-0 yr-pass overlaps the CSR build. Persistent GEMM blocks, light
// smem/regs so gather blocks co-reside with GEMM blocks on the same SMs.
// ---------------------------------------------------------------------------

#define N_NODES 100000
#define N_EDGES 1600000
#define LDXS 136   // A smem leading dim (half elems)
#define NSM 148

__device__ __half g_xh[(size_t)N_NODES * 128];
__device__ __half g_hA[(size_t)N_NODES * 128];
__device__ __half g_hB[(size_t)N_NODES * 128];
__device__ __half g_G [(size_t)N_NODES * 128];
__device__ float  g_yr[(size_t)N_NODES * 128];
__device__ int    g_cnt[N_NODES];
__device__ int    g_off[N_NODES];
__device__ int    g_cur[N_NODES];
__device__ int    g_csr[N_EDGES];
__device__ int    g_bsum[128];
__device__ int    g_is64;

// --------------------------- edge dtype probe ------------------------------
__global__ void detect_kernel(const void* ei) {
    const long long* e64 = (const long long*)ei;
    int is64 = 1;
    for (int i = 0; i < 64; i++) {
        long long v = e64[i];
        if (v < 0 || v >= N_NODES) { is64 = 0; break; }
    }
    g_is64 = is64;
}

__device__ __forceinline__ int load_idx(const void* ei, long long pos) {
    if (g_is64) return (int)((const long long*)ei)[pos];
    return ((const int*)ei)[pos];
}

// ------------------------------- CSR build ---------------------------------
__global__ void zero_int_kernel(int* __restrict__ p, int n) {
    int i = blockIdx.x * blockDim.x + threadIdx.x;
    if (i < n) p[i] = 0;
}

__global__ void hist_kernel(const void* __restrict__ ei, int* __restrict__ cnt) {
    int e = blockIdx.x * blockDim.x + threadIdx.x;
    if (e < N_EDGES) {
        int d = load_idx(ei, (long long)N_EDGES + e);
        if ((unsigned)d < N_NODES) atomicAdd(&cnt[d], 1);
    }
}

__global__ void blockreduce_kernel(const int* __restrict__ cnt, int* __restrict__ bsum) {
    __shared__ int sm[256];
    int b = blockIdx.x, t = threadIdx.x;
    int base = b * 1024 + t * 4;
    int s = 0;
    #pragma unroll
    for (int i = 0; i < 4; i++) {
        int idx = base + i;
        if (idx < N_NODES) s += cnt[idx];
    }
    sm[t] = s; __syncthreads();
    for (int st = 128; st > 0; st >>= 1) {
        if (t < st) sm[t] += sm[t + st];
        __syncthreads();
    }
    if (t == 0) bsum[b] = sm[0];
}

__global__ void scanpart_kernel(int* __restrict__ bsum, int nb) {
    if (threadIdx.x == 0) {
        int acc = 0;
        for (int i = 0; i < nb; i++) { int v = bsum[i]; bsum[i] = acc; acc += v; }
    }
}

__global__ void scanfinal_kernel(const int* __restrict__ cnt, const int* __restrict__ bsum,
                                 int* __restrict__ off, int* __restrict__ cur) {
    __shared__ int sm[256];
    int b = blockIdx.x, t = threadIdx.x;
    int base = b * 1024 + t * 4;
    int v[4]; int s = 0;
    #pragma unroll
    for (int i = 0; i < 4; i++) {
        int idx = base + i;
        v[i] = (idx < N_NODES) ? cnt[idx] : 0;
        s += v[i];
    }
    sm[t] = s; __syncthreads();
    for (int st = 1; st < 256; st <<= 1) {
        int x = (t >= st) ? sm[t - st] : 0;
        __syncthreads();
        sm[t] += x;
        __syncthreads();
    }
    int run = sm[t] - s + bsum[b];
    #pragma unroll
    for (int i = 0; i < 4; i++) {
        int idx = base + i;
        if (idx < N_NODES) { off[idx] = run; cur[idx] = run; }
        run += v[i];
    }
}

__global__ void fill_kernel(const void* __restrict__ ei, int* __restrict__ cur,
                            int* __restrict__ csr) {
    int e = blockIdx.x * blockDim.x + threadIdx.x;
    if (e < N_EDGES) {
        int s = load_idx(ei, e);
        int d = load_idx(ei, (long long)N_EDGES + e);
        if ((unsigned)s < N_NODES && (unsigned)d < N_NODES) {
            int p = atomicAdd(&cur[d], 1);
            csr[p] = s;
        }
    }
}

// ------------------------- x fp32 -> fp16 convert ---------------------------
__global__ void conv_f2h_kernel(const float* __restrict__ x, __half* __restrict__ xh, int n4) {
    int i = blockIdx.x * blockDim.x + threadIdx.x;
    if (i < n4) {
        float4 v = reinterpret_cast<const float4*>(x)[i];
        __half2 h0 = __floats2half2_rn(v.x, v.y);
        __half2 h1 = __floats2half2_rn(v.z, v.w);
        uint2 p;
        p.x = *reinterpret_cast<unsigned*>(&h0);
        p.y = *reinterpret_cast<unsigned*>(&h1);
        reinterpret_cast<uint2*>(xh)[i] = p;
    }
}

// ---------------------------------------------------------------------------
// Gather: G[n] = fp16( sum_{s in N(n)} h[s] )   (128 ch, one warp per node)
// ---------------------------------------------------------------------------
__device__ __forceinline__ void acc_h4(float4& acc, uint2 raw) {
    __half2 p0 = *reinterpret_cast<__half2*>(&raw.x);
    __half2 p1 = *reinterpret_cast<__half2*>(&raw.y);
    float2 f0 = __half22float2(p0);
    float2 f1 = __half22float2(p1);
    acc.x += f0.x; acc.y += f0.y; acc.z += f1.x; acc.w += f1.y;
}

__global__ __launch_bounds__(256) void gather128_h16_kernel(
    const __half* __restrict__ h,
    const int* __restrict__ csr, const int* __restrict__ off,
    const int* __restrict__ cnt, __half* __restrict__ G)
{
    int warp = (blockIdx.x * 256 + threadIdx.x) >> 5;
    int lane = threadIdx.x & 31;
    if (warp >= N_NODES) return;

    const int c = cnt[warp];
    const int o = off[warp];
    const uint2* __restrict__ h2 = reinterpret_cast<const uint2*>(h);

    float4 acc = make_float4(0.f, 0.f, 0.f, 0.f);
    int j = 0;
    for (; j + 4 <= c; j += 4) {
        int s0 = csr[o + j + 0];
        int s1 = csr[o + j + 1];
        int s2 = csr[o + j + 2];
        int s3 = csr[o + j + 3];
        uint2 a0 = h2[(size_t)s0 * 32 + lane];
        uint2 a1 = h2[(size_t)s1 * 32 + lane];
        uint2 a2 = h2[(size_t)s2 * 32 + lane];
        uint2 a3 = h2[(size_t)s3 * 32 + lane];
        acc_h4(acc, a0); acc_h4(acc, a1); acc_h4(acc, a2); acc_h4(acc, a3);
    }
    for (; j < c; j++) {
        int s = csr[o + j];
        acc_h4(acc, h2[(size_t)s * 32 + lane]);
    }
    __half2 o0 = __floats2half2_rn(acc.x, acc.y);
    __half2 o1 = __floats2half2_rn(acc.z, acc.w);
    uint2 p;
    p.x = *reinterpret_cast<unsigned*>(&o0);
    p.y = *reinterpret_cast<unsigned*>(&o1);
    reinterpret_cast<uint2*>(G)[(size_t)warp * 32 + lane] = p;
}

// ---------------------------------------------------------------------------
// Shared GEMM machinery: persistent, 512 thr, W split fp16 hi/lo once/block.
// Tiling: 16 warps = WM4 x WN4; warp = 32 rows (MFRAG=2) x DOUT/4 cols.
// ---------------------------------------------------------------------------
__device__ __forceinline__ void wsplit_stage(const float* __restrict__ W,
                                             __half* sWh, __half* sWl,
                                             int LDW, int C4, int t) {
    const float4* g = reinterpret_cast<const float4*>(W);
    for (int i = t; i < 128 * C4; i += 512) {
        int k = i / C4, c4 = i % C4;
        int so = k * LDW + c4 * 4;
        float4 w = g[i];
        __half hx = __float2half_rn(w.x), hy = __float2half_rn(w.y);
        __half hz = __float2half_rn(w.z), hw = __float2half_rn(w.w);
        sWh[so] = hx; sWh[so+1] = hy; sWh[so+2] = hz; sWh[so+3] = hw;
        sWl[so]   = __float2half_rn(w.x - __half2float(hx));
        sWl[so+1] = __float2half_rn(w.y - __half2float(hy));
        sWl[so+2] = __float2half_rn(w.z - __half2float(hz));
        sWl[so+3] = __float2half_rn(w.w - __half2float(hw));
    }
}

// ---- yr-pass: Yf(fp32) = H @ (Wh + Wl), direct fragment store ----
template <int DOUT>
__global__ __launch_bounds__(512) void gemm_yr(
    const __half* __restrict__ H, const float* __restrict__ W,
    float* __restrict__ Yf)
{
    constexpr int LDW = DOUT + 8;
    constexpr int NT = (N_NODES + 127) / 128;
    extern __shared__ __half smem[];
    __half* sH  = smem;                 // [128][LDXS]
    __half* sWh = sH + 128 * LDXS;      // [128][LDW]
    __half* sWl = sWh + 128 * LDW;

    const int t = threadIdx.x;
    wsplit_stage(W, sWh, sWl, LDW, DOUT / 4, t);

    constexpr int NF = DOUT / 64;       // 2 or 1
    const int warp = t >> 5;
    const int wm = warp & 3;
    const int wn = warp >> 2;
    const int mbase = wm * 32;
    const int nbase = wn * (DOUT / 4);

    const uint2* __restrict__ H2 = reinterpret_cast<const uint2*>(H);

    for (int tile = blockIdx.x; tile < NT; tile += gridDim.x) {
        const int row0 = tile * 128;

        for (int i = t; i < 128 * 32; i += 512) {
            int r = i >> 5, c = i & 31;
            int gr = row0 + r;
            uint2 hv = make_uint2(0u, 0u);
            if (gr < N_NODES) hv = H2[(size_t)gr * 32 + c];
            *reinterpret_cast<uint2*>(&sH[r * LDXS + c * 4]) = hv;
        }
        __syncthreads();

        wmma::fragment<wmma::accumulator, 16, 16, 16, float> acc[2][NF];
        #pragma unroll
        for (int mf = 0; mf < 2; mf++)
            #pragma unroll
            for (int nf = 0; nf < NF; nf++)
                wmma::fill_fragment(acc[mf][nf], 0.0f);

        #pragma unroll
        for (int k = 0; k < 128; k += 16) {
            wmma::fragment<wmma::matrix_a, 16, 16, 16, __half, wmma::row_major> a[2];
            #pragma unroll
            for (int mf = 0; mf < 2; mf++)
                wmma::load_matrix_sync(a[mf], &sH[(mbase + mf * 16) * LDXS + k], LDXS);
            #pragma unroll
            for (int nf = 0; nf < NF; nf++) {
                int n0 = nbase + nf * 16;
                wmma::fragment<wmma::matrix_b, 16, 16, 16, __half, wmma::row_major> bh, bl;
                wmma::load_matrix_sync(bh, &sWh[k * LDW + n0], LDW);
                wmma::load_matrix_sync(bl, &sWl[k * LDW + n0], LDW);
                #pragma unroll
                for (int mf = 0; mf < 2; mf++) {
                    wmma::mma_sync(acc[mf][nf], a[mf], bh, acc[mf][nf]);
                    wmma::mma_sync(acc[mf][nf], a[mf], bl, acc[mf][nf]);
                }
            }
        }

        #pragma unroll
        for (int mf = 0; mf < 2; mf++) {
            int grow = row0 + mbase + mf * 16;
            if (grow < N_NODES) {
                #pragma unroll
                for (int nf = 0; nf < NF; nf++)
                    wmma::store_matrix_sync(Yf + (size_t)grow * DOUT + nbase + nf * 16,
                                            acc[mf][nf], DOUT, wmma::mem_row_major);
            }
        }
        __syncthreads();   // sH consumed before next tile overwrite
    }
}

// ---- final-pass: out = act( (G/deg)@(Wh+Wl) + yr + b ) ----
template <int DOUT, bool RELU, bool F16OUT>
__global__ __launch_bounds__(512) void gemm_final(
    const __half* __restrict__ G, const int* __restrict__ cnt,
    const float* __restrict__ W, const float* __restrict__ yr,
    const float* __restrict__ bias,
    __half* __restrict__ Yh, float* __restrict__ Yf)
{
    constexpr int LDW = DOUT + 8;
    constexpr int LDE = DOUT + 4;
    constexpr int NT = (N_NODES + 127) / 128;
    extern __shared__ __half smem[];
    __half* sG  = smem;                 // [128][LDXS]
    __half* sWh = sG + 128 * LDXS;      // [128][LDW]
    __half* sWl = sWh + 128 * LDW;
    float*  sEp = reinterpret_cast<float*>(sWl + 128 * LDW);  // [128][LDE]

    const int t = threadIdx.x;
    wsplit_stage(W, sWh, sWl, LDW, DOUT / 4, t);

    constexpr int NF = DOUT / 64;
    const int warp = t >> 5;
    const int wm = warp & 3;
    const int wn = warp >> 2;
    const int mbase = wm * 32;
    const int nbase = wn * (DOUT / 4);

    const uint2* __restrict__ G2 = reinterpret_cast<const uint2*>(G);

    for (int tile = blockIdx.x; tile < NT; tile += gridDim.x) {
        const int row0 = tile * 128;

        for (int i = t; i < 128 * 32; i += 512) {
            int r = i >> 5, c = i & 31;
            int gr = row0 + r;
            uint2 gv = make_uint2(0u, 0u);
            if (gr < N_NODES) {
                gv = G2[(size_t)gr * 32 + c];
                float dinv = 1.0f / fmaxf((float)cnt[gr], 1.0f);
                __half2 p0 = *reinterpret_cast<__half2*>(&gv.x);
                __half2 p1 = *reinterpret_cast<__half2*>(&gv.y);
                float2 f0 = __half22float2(p0);
                float2 f1 = __half22float2(p1);
                __half2 q0 = __floats2half2_rn(f0.x * dinv, f0.y * dinv);
                __half2 q1 = __floats2half2_rn(f1.x * dinv, f1.y * dinv);
                gv.x = *reinterpret_cast<unsigned*>(&q0);
                gv.y = *reinterpret_cast<unsigned*>(&q1);
            }
            *reinterpret_cast<uint2*>(&sG[r * LDXS + c * 4]) = gv;
        }
        __syncthreads();

        wmma::fragment<wmma::accumulator, 16, 16, 16, float> acc[2][NF];
        #pragma unroll
        for (int mf = 0; mf < 2; mf++)
            #pragma unroll
            for (int nf = 0; nf < NF; nf++)
                wmma::fill_fragment(acc[mf][nf], 0.0f);

        #pragma unroll
        for (int k = 0; k < 128; k += 16) {
            wmma::fragment<wmma::matrix_a, 16, 16, 16, __half, wmma::row_major> a[2];
            #pragma unroll
            for (int mf = 0; mf < 2; mf++)
                wmma::load_matrix_sync(a[mf], &sG[(mbase + mf * 16) * LDXS + k], LDXS);
            #pragma unroll
            for (int nf = 0; nf < NF; nf++) {
                int n0 = nbase + nf * 16;
                wmma::fragment<wmma::matrix_b, 16, 16, 16, __half, wmma::row_major> bh, bl;
                wmma::load_matrix_sync(bh, &sWh[k * LDW + n0], LDW);
                wmma::load_matrix_sync(bl, &sWl[k * LDW + n0], LDW);
                #pragma unroll
                for (int mf = 0; mf < 2; mf++) {
                    wmma::mma_sync(acc[mf][nf], a[mf], bh, acc[mf][nf]);
                    wmma::mma_sync(acc[mf][nf], a[mf], bl, acc[mf][nf]);
                }
            }
        }

        // epilogue: restage in dedicated sEp, add yr + b, act, store
        #pragma unroll
        for (int mf = 0; mf < 2; mf++)
            #pragma unroll
            for (int nf = 0; nf < NF; nf++)
                wmma::store_matrix_sync(&sEp[(mbase + mf * 16) * LDE + nbase + nf * 16],
                                        acc[mf][nf], LDE, wmma::mem_row_major);
        __syncthreads();
        {
            constexpr int C4 = DOUT / 4;
            for (int i = t; i < 128 * C4; i += 512) {
                int r = i / C4, c4 = i % C4;
                int gr = row0 + r;
                if (gr < N_NODES) {
                    float4 v = *reinterpret_cast<const float4*>(&sEp[r * LDE + c4 * 4]);
                    float4 yv = reinterpret_cast<const float4*>(yr)[(size_t)gr * C4 + c4];
                    float4 bb = reinterpret_cast<const float4*>(bias)[c4];
                    v.x += yv.x + bb.x; v.y += yv.y + bb.y;
                    v.z += yv.z + bb.z; v.w += yv.w + bb.w;
                    if (RELU) {
                        v.x = fmaxf(v.x, 0.f); v.y = fmaxf(v.y, 0.f);
                        v.z = fmaxf(v.z, 0.f); v.w = fmaxf(v.w, 0.f);
                    }
                    if (F16OUT) {
                        __half2 h0 = __floats2half2_rn(v.x, v.y);
                        __half2 h1 = __floats2half2_rn(v.z, v.w);
                        uint2 p;
                        p.x = *reinterpret_cast<unsigned*>(&h0);
                        p.y = *reinterpret_cast<unsigned*>(&h1);
                        *reinterpret_cast<uint2*>(Yh + (size_t)gr * DOUT + c4 * 4) = p;
                    } else {
                        *reinterpret_cast<float4*>(Yf + (size_t)gr * DOUT + c4 * 4) = v;
                    }
                }
            }
        }
        __syncthreads();
    }
}

// ---------------------------------------------------------------------------
extern "C" void kernel_launch(void* const* d_in, const int* in_sizes, int n_in,
                              void* d_out, int out_size)
{
    const float* x   = (const float*)d_in[0];
    const void*  ei  = d_in[1];
    const float* Wl0 = (const float*)d_in[2];
    const float* Wr0 = (const float*)d_in[3];
    const float* b0  = (const float*)d_in[4];
    const float* Wl1 = (const float*)d_in[5];
    const float* Wr1 = (const float*)d_in[6];
    const float* b1  = (const float*)d_in[7];
    const float* Wl2 = (const float*)d_in[8];
    const float* Wr2 = (const float*)d_in[9];
    const float* b2  = (const float*)d_in[10];
    float* out = (float*)d_out;

    const int SM_H   = 128 * LDXS * (int)sizeof(__half);              // 34816
    const int SM_YR128  = SM_H + 2 * 128 * 136 * (int)sizeof(__half); // 104448
    const int SM_YR64   = SM_H + 2 * 128 * 72  * (int)sizeof(__half); // 71680
    const int SM_FIN128 = SM_YR128 + 128 * 132 * (int)sizeof(float);  // 172032
    const int SM_FIN64  = SM_YR64  + 128 * 68  * (int)sizeof(float);  // 106496

    static __half *p_xh = nullptr, *p_hA = nullptr, *p_hB = nullptr, *p_G = nullptr;
    static float *p_yr = nullptr;
    static int *p_cnt = nullptr, *p_off = nullptr, *p_cur = nullptr, *p_csr = nullptr, *p_bsum = nullptr;
    static cudaStream_t s_aux = nullptr;
    static cudaEvent_t ev[8];
    if (!p_xh) {
        cudaGetSymbolAddress((void**)&p_xh,   g_xh);
        cudaGetSymbolAddress((void**)&p_hA,   g_hA);
        cudaGetSymbolAddress((void**)&p_hB,   g_hB);
        cudaGetSymbolAddress((void**)&p_G,    g_G);
        cudaGetSymbolAddress((void**)&p_yr,   g_yr);
        cudaGetSymbolAddress((void**)&p_cnt,  g_cnt);
        cudaGetSymbolAddress((void**)&p_off,  g_off);
        cudaGetSymbolAddress((void**)&p_cur,  g_cur);
        cudaGetSymbolAddress((void**)&p_csr,  g_csr);
        cudaGetSymbolAddress((void**)&p_bsum, g_bsum);
        cudaStreamCreateWithFlags(&s_aux, cudaStreamNonBlocking);
        for (int i = 0; i < 8; i++)
            cudaEventCreateWithFlags(&ev[i], cudaEventDisableTiming);
        cudaFuncSetAttribute(gemm_yr<128>, cudaFuncAttributeMaxDynamicSharedMemorySize, SM_YR128);
        cudaFuncSetAttribute(gemm_yr<64>,  cudaFuncAttributeMaxDynamicSharedMemorySize, SM_YR64);
        cudaFuncSetAttribute(gemm_final<128, true, true>,
                             cudaFuncAttributeMaxDynamicSharedMemorySize, SM_FIN128);
        cudaFuncSetAttribute(gemm_final<64, false, false>,
                             cudaFuncAttributeMaxDynamicSharedMemorySize, SM_FIN64);
    }

    const int NB_SCAN = (N_NODES + 1023) / 1024;
    const int NB_EDGE = (N_EDGES + 255) / 256;
    const int NB_G128 = (N_NODES * 32 + 255) / 256;
    const int NB_CONV = (N_NODES * 32 + 255) / 256;

    // x -> fp16 first (gather0 needs it on aux)
    conv_f2h_kernel<<<NB_CONV, 256>>>(x, p_xh, N_NODES * 32);
    cudaEventRecord(ev[0], 0);
    cudaStreamWaitEvent(s_aux, ev[0], 0);

    // aux: CSR build + gather0(xh)  — overlaps yr0 on main
    detect_kernel<<<1, 1, 0, s_aux>>>(ei);
    zero_int_kernel<<<(N_NODES + 255) / 256, 256, 0, s_aux>>>(p_cnt, N_NODES);
    hist_kernel<<<NB_EDGE, 256, 0, s_aux>>>(ei, p_cnt);
    blockreduce_kernel<<<NB_SCAN, 256, 0, s_aux>>>(p_cnt, p_bsum);
    scanpart_kernel<<<1, 32, 0, s_aux>>>(p_bsum, NB_SCAN);
    scanfinal_kernel<<<NB_SCAN, 256, 0, s_aux>>>(p_cnt, p_bsum, p_off, p_cur);
    fill_kernel<<<NB_EDGE, 256, 0, s_aux>>>(ei, p_cur, p_csr);
    gather128_h16_kernel<<<NB_G128, 256, 0, s_aux>>>(p_xh, p_csr, p_off, p_cnt, p_G);
    cudaEventRecord(ev[1], s_aux);

    // ---- Layer 0 ----
    gemm_yr<128><<<NSM, 512, SM_YR128>>>(p_xh, Wr0, p_yr);
    cudaStreamWaitEvent(0, ev[1], 0);
    gemm_final<128, true, true><<<NSM, 512, SM_FIN128>>>(
        p_G, p_cnt, Wl0, p_yr, b0, p_hA, nullptr);
    cudaEventRecord(ev[2], 0);

    // ---- Layer 1: gather1 (aux) || yr1 (main) ----
    cudaStreamWaitEvent(s_aux, ev[2], 0);
    gather128_h16_kernel<<<NB_G128, 256, 0, s_aux>>>(p_hA, p_csr, p_off, p_cnt, p_G);
    cudaEventRecord(ev[3], s_aux);
    gemm_yr<128><<<NSM, 512, SM_YR128>>>(p_hA, Wr1, p_yr);
    cudaStreamWaitEvent(0, ev[3], 0);
    gemm_final<128, true, true><<<NSM, 512, SM_FIN128>>>(
        p_G, p_cnt, Wl1, p_yr, b1, p_hB, nullptr);
    cudaEventRecord(ev[4], 0);

    // ---- Layer 2: gather2 (aux) || yr2 (main); 64-ch out ----
    cudaStreamWaitEvent(s_aux, ev[4], 0);
    gather128_h16_kernel<<<NB_G128, 256, 0, s_aux>>>(p_hB, p_csr, p_off, p_cnt, p_G);
    cudaEventRecord(ev[5], s_aux);
    gemm_yr<64><<<NSM, 512, SM_YR64>>>(p_hB, Wr2, p_yr);
    cudaStreamWaitEvent(0, ev[5], 0);
    gemm_final<64, false, false><<<NSM, 512, SM_FIN64>>>(
        p_G, p_cnt, Wl2, p_yr, b2, nullptr, out);
}

// round 17
// speedup vs baseline: 1.3099x; 1.3099x over previous
#include <cuda_runtime.h>
#include <cuda_fp16.h>
#include <mma.h>
#include <cstdint>

using namespace nvcuda;

// ---------------------------------------------------------------------------
// GraphSAGE 3-layer, fp16 activations.
// Layer 0: transform-then-aggregate (graph-independent dual GEMM overlaps the
//          CSR build):  yl=x@Wl0, yr=x@Wr0  ||  CSR on aux
//          then h1 = relu(gather(yl)/deg + yr + b0)   (combine kernel)
// Layers 1-2: R15 fused aggregate-then-transform (proven fastest):
//          h' = act( (gather(h)/deg)@Wl + h@Wr + b )  in ONE GEMM.
// W split fp16 hi/lo in-kernel; persistent GEMM blocks; WM4xWN4xMFRAG2.
// ---------------------------------------------------------------------------

#define N_NODES 100000
#define N_EDGES 1600000
#define LDXS 136
#define NSM 148

__device__ __half g_xh[(size_t)N_NODES * 128];
__device__ __half g_hA[(size_t)N_NODES * 128];
__device__ __half g_hB[(size_t)N_NODES * 128];
__device__ __half g_G [(size_t)N_NODES * 128];
__device__ float  g_yr[(size_t)N_NODES * 128];
__device__ int    g_cnt[N_NODES];
__device__ int    g_off[N_NODES];
__device__ int    g_cur[N_NODES];
__device__ int    g_csr[N_EDGES];
__device__ int    g_bsum[128];
__device__ int    g_is64;

// --------------------------- edge dtype probe ------------------------------
__global__ void detect_kernel(const void* ei) {
    const long long* e64 = (const long long*)ei;
    int is64 = 1;
    for (int i = 0; i < 64; i++) {
        long long v = e64[i];
        if (v < 0 || v >= N_NODES) { is64 = 0; break; }
    }
    g_is64 = is64;
}

__device__ __forceinline__ int load_idx(const void* ei, long long pos) {
    if (g_is64) return (int)((const long long*)ei)[pos];
    return ((const int*)ei)[pos];
}

// ------------------------------- CSR build ---------------------------------
__global__ void zero_int_kernel(int* __restrict__ p, int n) {
    int i = blockIdx.x * blockDim.x + threadIdx.x;
    if (i < n) p[i] = 0;
}

__global__ void hist_kernel(const void* __restrict__ ei, int* __restrict__ cnt) {
    int e = blockIdx.x * blockDim.x + threadIdx.x;
    if (e < N_EDGES) {
        int d = load_idx(ei, (long long)N_EDGES + e);
        if ((unsigned)d < N_NODES) atomicAdd(&cnt[d], 1);
    }
}

__global__ void blockreduce_kernel(const int* __restrict__ cnt, int* __restrict__ bsum) {
    __shared__ int sm[256];
    int b = blockIdx.x, t = threadIdx.x;
    int base = b * 1024 + t * 4;
    int s = 0;
    #pragma unroll
    for (int i = 0; i < 4; i++) {
        int idx = base + i;
        if (idx < N_NODES) s += cnt[idx];
    }
    sm[t] = s; __syncthreads();
    for (int st = 128; st > 0; st >>= 1) {
        if (t < st) sm[t] += sm[t + st];
        __syncthreads();
    }
    if (t == 0) bsum[b] = sm[0];
}

__global__ void scanpart_kernel(int* __restrict__ bsum, int nb) {
    if (threadIdx.x == 0) {
        int acc = 0;
        for (int i = 0; i < nb; i++) { int v = bsum[i]; bsum[i] = acc; acc += v; }
    }
}

__global__ void scanfinal_kernel(const int* __restrict__ cnt, const int* __restrict__ bsum,
                                 int* __restrict__ off, int* __restrict__ cur) {
    __shared__ int sm[256];
    int b = blockIdx.x, t = threadIdx.x;
    int base = b * 1024 + t * 4;
    int v[4]; int s = 0;
    #pragma unroll
    for (int i = 0; i < 4; i++) {
        int idx = base + i;
        v[i] = (idx < N_NODES) ? cnt[idx] : 0;
        s += v[i];
    }
    sm[t] = s; __syncthreads();
    for (int st = 1; st < 256; st <<= 1) {
        int x = (t >= st) ? sm[t - st] : 0;
        __syncthreads();
        sm[t] += x;
        __syncthreads();
    }
    int run = sm[t] - s + bsum[b];
    #pragma unroll
    for (int i = 0; i < 4; i++) {
        int idx = base + i;
        if (idx < N_NODES) { off[idx] = run; cur[idx] = run; }
        run += v[i];
    }
}

__global__ void fill_kernel(const void* __restrict__ ei, int* __restrict__ cur,
                            int* __restrict__ csr) {
    int e = blockIdx.x * blockDim.x + threadIdx.x;
    if (e < N_EDGES) {
        int s = load_idx(ei, e);
        int d = load_idx(ei, (long long)N_EDGES + e);
        if ((unsigned)s < N_NODES && (unsigned)d < N_NODES) {
            int p = atomicAdd(&cur[d], 1);
            csr[p] = s;
        }
    }
}

// ------------------------- x fp32 -> fp16 convert ---------------------------
__global__ void conv_f2h_kernel(const float* __restrict__ x, __half* __restrict__ xh, int n4) {
    int i = blockIdx.x * blockDim.x + threadIdx.x;
    if (i < n4) {
        float4 v = reinterpret_cast<const float4*>(x)[i];
        __half2 h0 = __floats2half2_rn(v.x, v.y);
        __half2 h1 = __floats2half2_rn(v.z, v.w);
        uint2 p;
        p.x = *reinterpret_cast<unsigned*>(&h0);
        p.y = *reinterpret_cast<unsigned*>(&h1);
        reinterpret_cast<uint2*>(xh)[i] = p;
    }
}

// ---------------------------------------------------------------------------
// Gather: G[n] = fp16( sum_{s in N(n)} h[s] )   (128 ch, one warp per node)
// ---------------------------------------------------------------------------
__device__ __forceinline__ void acc_h4(float4& acc, uint2 raw) {
    __half2 p0 = *reinterpret_cast<__half2*>(&raw.x);
    __half2 p1 = *reinterpret_cast<__half2*>(&raw.y);
    float2 f0 = __half22float2(p0);
    float2 f1 = __half22float2(p1);
    acc.x += f0.x; acc.y += f0.y; acc.z += f1.x; acc.w += f1.y;
}

__global__ __launch_bounds__(256) void gather128_h16_kernel(
    const __half* __restrict__ h,
    const int* __restrict__ csr, const int* __restrict__ off,
    const int* __restrict__ cnt, __half* __restrict__ G)
{
    int warp = (blockIdx.x * 256 + threadIdx.x) >> 5;
    int lane = threadIdx.x & 31;
    if (warp >= N_NODES) return;

    const int c = cnt[warp];
    const int o = off[warp];
    const uint2* __restrict__ h2 = reinterpret_cast<const uint2*>(h);

    float4 acc = make_float4(0.f, 0.f, 0.f, 0.f);
    int j = 0;
    for (; j + 4 <= c; j += 4) {
        int s0 = csr[o + j + 0];
        int s1 = csr[o + j + 1];
        int s2 = csr[o + j + 2];
        int s3 = csr[o + j + 3];
        uint2 a0 = h2[(size_t)s0 * 32 + lane];
        uint2 a1 = h2[(size_t)s1 * 32 + lane];
        uint2 a2 = h2[(size_t)s2 * 32 + lane];
        uint2 a3 = h2[(size_t)s3 * 32 + lane];
        acc_h4(acc, a0); acc_h4(acc, a1); acc_h4(acc, a2); acc_h4(acc, a3);
    }
    for (; j < c; j++) {
        int s = csr[o + j];
        acc_h4(acc, h2[(size_t)s * 32 + lane]);
    }
    __half2 o0 = __floats2half2_rn(acc.x, acc.y);
    __half2 o1 = __floats2half2_rn(acc.z, acc.w);
    uint2 p;
    p.x = *reinterpret_cast<unsigned*>(&o0);
    p.y = *reinterpret_cast<unsigned*>(&o1);
    reinterpret_cast<uint2*>(G)[(size_t)warp * 32 + lane] = p;
}

// ---------------------------------------------------------------------------
// Combine (layer 0 only): h1 = fp16( relu(G/deg + yr + b) )
// ---------------------------------------------------------------------------
__global__ __launch_bounds__(256) void combine_kernel(
    const __half* __restrict__ G, const float* __restrict__ yr,
    const float* __restrict__ b, const int* __restrict__ cnt,
    __half* __restrict__ h1)
{
    int i = blockIdx.x * blockDim.x + threadIdx.x;
    if (i >= N_NODES * 32) return;
    int node = i >> 5;
    int c = i & 31;

    float dinv = 1.0f / fmaxf((float)cnt[node], 1.0f);
    uint2 gv = reinterpret_cast<const uint2*>(G)[i];
    __half2 p0 = *reinterpret_cast<__half2*>(&gv.x);
    __half2 p1 = *reinterpret_cast<__half2*>(&gv.y);
    float2 f0 = __half22float2(p0);
    float2 f1 = __half22float2(p1);
    float4 yv = reinterpret_cast<const float4*>(yr)[i];
    float4 bb = reinterpret_cast<const float4*>(b)[c];
    float4 v;
    v.x = fmaxf(f0.x * dinv + yv.x + bb.x, 0.f);
    v.y = fmaxf(f0.y * dinv + yv.y + bb.y, 0.f);
    v.z = fmaxf(f1.x * dinv + yv.z + bb.z, 0.f);
    v.w = fmaxf(f1.y * dinv + yv.w + bb.w, 0.f);
    __half2 h0 = __floats2half2_rn(v.x, v.y);
    __half2 h1v = __floats2half2_rn(v.z, v.w);
    uint2 p;
    p.x = *reinterpret_cast<unsigned*>(&h0);
    p.y = *reinterpret_cast<unsigned*>(&h1v);
    reinterpret_cast<uint2*>(h1)[i] = p;
}

// ---------------------------------------------------------------------------
// W split helper: fp32 W -> fp16 hi/lo in smem
// ---------------------------------------------------------------------------
__device__ __forceinline__ void wsplit_stage(const float* __restrict__ W,
                                             __half* sWh, __half* sWl,
                                             int LDW, int C4, int t) {
    const float4* g = reinterpret_cast<const float4*>(W);
    for (int i = t; i < 128 * C4; i += 512) {
        int k = i / C4, c4 = i % C4;
        int so = k * LDW + c4 * 4;
        float4 w = g[i];
        __half hx = __float2half_rn(w.x), hy = __float2half_rn(w.y);
        __half hz = __float2half_rn(w.z), hw = __float2half_rn(w.w);
        sWh[so] = hx; sWh[so+1] = hy; sWh[so+2] = hz; sWh[so+3] = hw;
        sWl[so]   = __float2half_rn(w.x - __half2float(hx));
        sWl[so+1] = __float2half_rn(w.y - __half2float(hy));
        sWl[so+2] = __float2half_rn(w.z - __half2float(hz));
        sWl[so+3] = __float2half_rn(w.w - __half2float(hw));
    }
}

// ---------------------------------------------------------------------------
// Layer-0 dual GEMM (persistent, graph-independent):
//   Ylh(fp16) = H@(Wlh+Wll),  Yr(fp32) = H@(Wrh+Wrl)
// One A prologue; Yr direct fragment store; Ylh via two-pass smem restage
// (sEp reuses the A region, 64 cols at a time).
// ---------------------------------------------------------------------------
__global__ __launch_bounds__(512) void gemm_dual0(
    const __half* __restrict__ H,
    const float* __restrict__ Wl, const float* __restrict__ Wr,
    __half* __restrict__ Ylh, float* __restrict__ Yr)
{
    constexpr int DOUT = 128;
    constexpr int LDW = DOUT + 8;
    constexpr int NT = (N_NODES + 127) / 128;
    extern __shared__ __half smem[];
    __half* sH   = smem;                  // [128][LDXS]  (34816 B)
    __half* sWlh = sH + 128 * LDXS;       // [128][LDW]
    __half* sWll = sWlh + 128 * LDW;
    __half* sWrh = sWll + 128 * LDW;
    __half* sWrl = sWrh + 128 * LDW;

    const int t = threadIdx.x;
    wsplit_stage(Wl, sWlh, sWll, LDW, DOUT / 4, t);
    wsplit_stage(Wr, sWrh, sWrl, LDW, DOUT / 4, t);

    constexpr int NF = 2;                  // DOUT/64
    const int warp = t >> 5;
    const int wm = warp & 3;
    const int wn = warp >> 2;
    const int mbase = wm * 32;
    const int nbase = wn * 32;             // DOUT/4

    const uint2* __restrict__ H2 = reinterpret_cast<const uint2*>(H);

    for (int tile = blockIdx.x; tile < NT; tile += gridDim.x) {
        const int row0 = tile * 128;

        for (int i = t; i < 128 * 32; i += 512) {
            int r = i >> 5, c = i & 31;
            int gr = row0 + r;
            uint2 hv = make_uint2(0u, 0u);
            if (gr < N_NODES) hv = H2[(size_t)gr * 32 + c];
            *reinterpret_cast<uint2*>(&sH[r * LDXS + c * 4]) = hv;
        }
        __syncthreads();

        wmma::fragment<wmma::accumulator, 16, 16, 16, float> accl[2][NF], accr[2][NF];
        #pragma unroll
        for (int mf = 0; mf < 2; mf++)
            #pragma unroll
            for (int nf = 0; nf < NF; nf++) {
                wmma::fill_fragment(accl[mf][nf], 0.0f);
                wmma::fill_fragment(accr[mf][nf], 0.0f);
            }

        #pragma unroll
        for (int k = 0; k < 128; k += 16) {
            wmma::fragment<wmma::matrix_a, 16, 16, 16, __half, wmma::row_major> a[2];
            #pragma unroll
            for (int mf = 0; mf < 2; mf++)
                wmma::load_matrix_sync(a[mf], &sH[(mbase + mf * 16) * LDXS + k], LDXS);
            #pragma unroll
            for (int nf = 0; nf < NF; nf++) {
                int n0 = nbase + nf * 16;
                wmma::fragment<wmma::matrix_b, 16, 16, 16, __half, wmma::row_major> blh, bll, brh, brl;
                wmma::load_matrix_sync(blh, &sWlh[k * LDW + n0], LDW);
                wmma::load_matrix_sync(bll, &sWll[k * LDW + n0], LDW);
                wmma::load_matrix_sync(brh, &sWrh[k * LDW + n0], LDW);
                wmma::load_matrix_sync(brl, &sWrl[k * LDW + n0], LDW);
                #pragma unroll
                for (int mf = 0; mf < 2; mf++) {
                    wmma::mma_sync(accl[mf][nf], a[mf], blh, accl[mf][nf]);
                    wmma::mma_sync(accl[mf][nf], a[mf], bll, accl[mf][nf]);
                    wmma::mma_sync(accr[mf][nf], a[mf], brh, accr[mf][nf]);
                    wmma::mma_sync(accr[mf][nf], a[mf], brl, accr[mf][nf]);
                }
            }
        }

        // Yr: direct fp32 fragment store
        #pragma unroll
        for (int mf = 0; mf < 2; mf++) {
            int grow = row0 + mbase + mf * 16;
            if (grow < N_NODES) {
                #pragma unroll
                for (int nf = 0; nf < NF; nf++)
                    wmma::store_matrix_sync(Yr + (size_t)grow * DOUT + nbase + nf * 16,
                                            accr[mf][nf], DOUT, wmma::mem_row_major);
            }
        }

        // Ylh: two-pass restage (64 cols at a time) in the sH region
        constexpr int LDE2 = 68;
        float* sEp = reinterpret_cast<float*>(smem);   // [128][68] = 34816 B
        #pragma unroll
        for (int hh = 0; hh < 2; hh++) {
            __syncthreads();
            if ((wn >> 1) == hh) {
                #pragma unroll
                for (int mf = 0; mf < 2; mf++)
                    #pragma unroll
                    for (int nf = 0; nf < NF; nf++)
                        wmma::store_matrix_sync(
                            &sEp[(mbase + mf * 16) * LDE2 + (nbase - hh * 64) + nf * 16],
                            accl[mf][nf], LDE2, wmma::mem_row_major);
            }
            __syncthreads();
            for (int i = t; i < 128 * 16; i += 512) {
                int r = i >> 4, c4 = i & 15;
                int gr = row0 + r;
                if (gr < N_NODES) {
                    float4 v = *reinterpret_cast<const float4*>(&sEp[r * LDE2 + c4 * 4]);
                    __half2 h0 = __floats2half2_rn(v.x, v.y);
                    __half2 h1 = __floats2half2_rn(v.z, v.w);
                    uint2 p;
                    p.x = *reinterpret_cast<unsigned*>(&h0);
                    p.y = *reinterpret_cast<unsigned*>(&h1);
                    *reinterpret_cast<uint2*>(Ylh + (size_t)gr * DOUT + hh * 64 + c4 * 4) = p;
                }
            }
        }
        __syncthreads();
    }
}

// ---------------------------------------------------------------------------
// Fused layer GEMM (layers 1-2, R15 winner):
//   acc = (G/deg)@Wlh + (G/deg)@Wll + H@Wrh + H@Wrl;  out = act(acc + b)
// ---------------------------------------------------------------------------
template <int DOUT, bool RELU, bool F16OUT>
__global__ __launch_bounds__(512) void gemm_fused(
    const __half* __restrict__ G, const __half* __restrict__ H,
    const int* __restrict__ cnt,
    const float* __restrict__ Wl, const float* __restrict__ Wr,
    const float* __restrict__ bias,
    __half* __restrict__ Yh, float* __restrict__ Yf)
{
    constexpr int LDW = DOUT + 8;
    constexpr int NT = (N_NODES + 127) / 128;
    extern __shared__ __half smem[];
    __half* sG   = smem;                    // [128][LDXS]
    __half* sH   = sG + 128 * LDXS;         // [128][LDXS]
    __half* sWlh = sH + 128 * LDXS;         // [128][LDW]
    __half* sWll = sWlh + 128 * LDW;
    __half* sWrh = sWll + 128 * LDW;
    __half* sWrl = sWrh + 128 * LDW;

    const int t = threadIdx.x;
    wsplit_stage(Wl, sWlh, sWll, LDW, DOUT / 4, t);
    wsplit_stage(Wr, sWrh, sWrl, LDW, DOUT / 4, t);

    constexpr int NF = DOUT / 64;
    const int warp = t >> 5;
    const int wm = warp & 3;
    const int wn = warp >> 2;
    const int mbase = wm * 32;
    const int nbase = wn * (DOUT / 4);

    const uint2* __restrict__ G2 = reinterpret_cast<const uint2*>(G);
    const uint2* __restrict__ H2 = reinterpret_cast<const uint2*>(H);

    for (int tile = blockIdx.x; tile < NT; tile += gridDim.x) {
        const int row0 = tile * 128;

        for (int i = t; i < 128 * 32; i += 512) {
            int r = i >> 5, c = i & 31;
            int gr = row0 + r;
            uint2 gv = make_uint2(0u, 0u);
            uint2 hv = make_uint2(0u, 0u);
            if (gr < N_NODES) {
                gv = G2[(size_t)gr * 32 + c];
                hv = H2[(size_t)gr * 32 + c];
                float dinv = 1.0f / fmaxf((float)cnt[gr], 1.0f);
                __half2 p0 = *reinterpret_cast<__half2*>(&gv.x);
                __half2 p1 = *reinterpret_cast<__half2*>(&gv.y);
                float2 f0 = __half22float2(p0);
                float2 f1 = __half22float2(p1);
                __half2 q0 = __floats2half2_rn(f0.x * dinv, f0.y * dinv);
                __half2 q1 = __floats2half2_rn(f1.x * dinv, f1.y * dinv);
                gv.x = *reinterpret_cast<unsigned*>(&q0);
                gv.y = *reinterpret_cast<unsigned*>(&q1);
            }
            int base = r * LDXS + c * 4;
            *reinterpret_cast<uint2*>(&sG[base]) = gv;
            *reinterpret_cast<uint2*>(&sH[base]) = hv;
        }
        __syncthreads();

        wmma::fragment<wmma::accumulator, 16, 16, 16, float> acc[2][NF];
        #pragma unroll
        for (int mf = 0; mf < 2; mf++)
            #pragma unroll
            for (int nf = 0; nf < NF; nf++)
                wmma::fill_fragment(acc[mf][nf], 0.0f);

        #pragma unroll
        for (int k = 0; k < 128; k += 16) {
            wmma::fragment<wmma::matrix_a, 16, 16, 16, __half, wmma::row_major> ga[2], ha[2];
            #pragma unroll
            for (int mf = 0; mf < 2; mf++) {
                wmma::load_matrix_sync(ga[mf], &sG[(mbase + mf * 16) * LDXS + k], LDXS);
                wmma::load_matrix_sync(ha[mf], &sH[(mbase + mf * 16) * LDXS + k], LDXS);
            }
            #pragma unroll
            for (int nf = 0; nf < NF; nf++) {
                int n0 = nbase + nf * 16;
                wmma::fragment<wmma::matrix_b, 16, 16, 16, __half, wmma::row_major> blh, bll, brh, brl;
                wmma::load_matrix_sync(blh, &sWlh[k * LDW + n0], LDW);
                wmma::load_matrix_sync(bll, &sWll[k * LDW + n0], LDW);
                wmma::load_matrix_sync(brh, &sWrh[k * LDW + n0], LDW);
                wmma::load_matrix_sync(brl, &sWrl[k * LDW + n0], LDW);
                #pragma unroll
                for (int mf = 0; mf < 2; mf++) {
                    wmma::mma_sync(acc[mf][nf], ga[mf], blh, acc[mf][nf]);
                    wmma::mma_sync(acc[mf][nf], ga[mf], bll, acc[mf][nf]);
                    wmma::mma_sync(acc[mf][nf], ha[mf], brh, acc[mf][nf]);
                    wmma::mma_sync(acc[mf][nf], ha[mf], brl, acc[mf][nf]);
                }
            }
        }

        constexpr int LDE = DOUT + 4;
        float* sEp = reinterpret_cast<float*>(smem);   // fits in sG+sH region
        __syncthreads();
        #pragma unroll
        for (int mf = 0; mf < 2; mf++)
            #pragma unroll
            for (int nf = 0; nf < NF; nf++)
                wmma::store_matrix_sync(&sEp[(mbase + mf * 16) * LDE + nbase + nf * 16],
                                        acc[mf][nf], LDE, wmma::mem_row_major);
        __syncthreads();
        {
            constexpr int C4 = DOUT / 4;
            for (int i = t; i < 128 * C4; i += 512) {
                int r = i / C4, c4 = i % C4;
                int gr = row0 + r;
                if (gr < N_NODES) {
                    float4 v = *reinterpret_cast<const float4*>(&sEp[r * LDE + c4 * 4]);
                    float4 bb = reinterpret_cast<const float4*>(bias)[c4];
                    v.x += bb.x; v.y += bb.y; v.z += bb.z; v.w += bb.w;
                    if (RELU) {
                        v.x = fmaxf(v.x, 0.f); v.y = fmaxf(v.y, 0.f);
                        v.z = fmaxf(v.z, 0.f); v.w = fmaxf(v.w, 0.f);
                    }
                    if (F16OUT) {
                        __half2 h0 = __floats2half2_rn(v.x, v.y);
                        __half2 h1 = __floats2half2_rn(v.z, v.w);
                        uint2 p;
                        p.x = *reinterpret_cast<unsigned*>(&h0);
                        p.y = *reinterpret_cast<unsigned*>(&h1);
                        *reinterpret_cast<uint2*>(Yh + (size_t)gr * DOUT + c4 * 4) = p;
                    } else {
                        *reinterpret_cast<float4*>(Yf + (size_t)gr * DOUT + c4 * 4) = v;
                    }
                }
            }
        }
        __syncthreads();
    }
}

// ---------------------------------------------------------------------------
extern "C" void kernel_launch(void* const* d_in, const int* in_sizes, int n_in,
                              void* d_out, int out_size)
{
    const float* x   = (const float*)d_in[0];
    const void*  ei  = d_in[1];
    const float* Wl0 = (const float*)d_in[2];
    const float* Wr0 = (const float*)d_in[3];
    const float* b0  = (const float*)d_in[4];
    const float* Wl1 = (const float*)d_in[5];
    const float* Wr1 = (const float*)d_in[6];
    const float* b1  = (const float*)d_in[7];
    const float* Wl2 = (const float*)d_in[8];
    const float* Wr2 = (const float*)d_in[9];
    const float* b2  = (const float*)d_in[10];
    float* out = (float*)d_out;

    const int SM_A      = 128 * LDXS * (int)sizeof(__half);                    // 34816
    const int SM_DUAL0  = SM_A + 4 * 128 * 136 * (int)sizeof(__half);          // 174080
    const int SM_F128   = 2 * SM_A + 4 * 128 * 136 * (int)sizeof(__half);      // 208896
    const int SM_F64    = 2 * SM_A + 4 * 128 * 72  * (int)sizeof(__half);      // 143360

    static __half *p_xh = nullptr, *p_hA = nullptr, *p_hB = nullptr, *p_G = nullptr;
    static float *p_yr = nullptr;
    static int *p_cnt = nullptr, *p_off = nullptr, *p_cur = nullptr, *p_csr = nullptr, *p_bsum = nullptr;
    static cudaStream_t s_aux = nullptr;
    static cudaEvent_t ev[4];
    if (!p_xh) {
        cudaGetSymbolAddress((void**)&p_xh,   g_xh);
        cudaGetSymbolAddress((void**)&p_hA,   g_hA);
        cudaGetSymbolAddress((void**)&p_hB,   g_hB);
        cudaGetSymbolAddress((void**)&p_G,    g_G);
        cudaGetSymbolAddress((void**)&p_yr,   g_yr);
        cudaGetSymbolAddress((void**)&p_cnt,  g_cnt);
        cudaGetSymbolAddress((void**)&p_off,  g_off);
        cudaGetSymbolAddress((void**)&p_cur,  g_cur);
        cudaGetSymbolAddress((void**)&p_csr,  g_csr);
        cudaGetSymbolAddress((void**)&p_bsum, g_bsum);
        cudaStreamCreateWithFlags(&s_aux, cudaStreamNonBlocking);
        for (int i = 0; i < 4; i++)
            cudaEventCreateWithFlags(&ev[i], cudaEventDisableTiming);
        cudaFuncSetAttribute(gemm_dual0,
                             cudaFuncAttributeMaxDynamicSharedMemorySize, SM_DUAL0);
        cudaFuncSetAttribute(gemm_fused<128, true, true>,
                             cudaFuncAttributeMaxDynamicSharedMemorySize, SM_F128);
        cudaFuncSetAttribute(gemm_fused<64, false, false>,
                             cudaFuncAttributeMaxDynamicSharedMemorySize, SM_F64);
    }

    const int NB_SCAN = (N_NODES + 1023) / 1024;
    const int NB_EDGE = (N_EDGES + 255) / 256;
    const int NB_G128 = (N_NODES * 32 + 255) / 256;
    const int NB_CONV = (N_NODES * 32 + 255) / 256;

    // Fork aux: CSR build runs concurrently with conv + dual GEMM0 (graph-free).
    cudaEventRecord(ev[0], 0);
    cudaStreamWaitEvent(s_aux, ev[0], 0);
    detect_kernel<<<1, 1, 0, s_aux>>>(ei);
    zero_int_kernel<<<(N_NODES + 255) / 256, 256, 0, s_aux>>>(p_cnt, N_NODES);
    hist_kernel<<<NB_EDGE, 256, 0, s_aux>>>(ei, p_cnt);
    blockreduce_kernel<<<NB_SCAN, 256, 0, s_aux>>>(p_cnt, p_bsum);
    scanpart_kernel<<<1, 32, 0, s_aux>>>(p_bsum, NB_SCAN);
    scanfinal_kernel<<<NB_SCAN, 256, 0, s_aux>>>(p_cnt, p_bsum, p_off, p_cur);
    fill_kernel<<<NB_EDGE, 256, 0, s_aux>>>(ei, p_cur, p_csr);
    cudaEventRecord(ev[1], s_aux);

    // Main: conv + layer-0 dual GEMM (CSR hidden underneath)
    conv_f2h_kernel<<<NB_CONV, 256>>>(x, p_xh, N_NODES * 32);
    gemm_dual0<<<NSM, 512, SM_DUAL0>>>(p_xh, Wl0, Wr0, p_hB /*yl scratch*/, p_yr);

    // Join: gather(yl) + combine -> h1
    cudaStreamWaitEvent(0, ev[1], 0);
    gather128_h16_kernel<<<NB_G128, 256>>>(p_hB, p_csr, p_off, p_cnt, p_G);
    combine_kernel<<<NB_G128, 256>>>(p_G, p_yr, b0, p_cnt, p_hA);

    // ---- Layer 1 (fused) ----
    gather128_h16_kernel<<<NB_G128, 256>>>(p_hA, p_csr, p_off, p_cnt, p_G);
    gemm_fused<128, true, true><<<NSM, 512, SM_F128>>>(
        p_G, p_hA, p_cnt, Wl1, Wr1, b1, p_hB, nullptr);

    // ---- Layer 2 (fused, 64 out, fp32 -> d_out) ----
    gather128_h16_kernel<<<NB_G128, 256>>>(p_hB, p_csr, p_off, p_cnt, p_G);
    gemm_fused<64, false, false><<<NSM, 512, SM_F64>>>(
        p_G, p_hB, p_cnt, Wl2, Wr2, b2, nullptr, out);
}